// round 14
// baseline (speedup 1.0000x reference)
#include <cuda_runtime.h>
#include <cuda_bf16.h>
#include <cstdint>

#define NROWS 16384
#define BDIM  8192
#define DDIM  128
#define THREADS 256
#define SM_A    0
#define SM_B    16384
#define SM_RED  32768
#define SM_TOTAL (32768 + 3072)   // A16K + B16K + red 3K -> tiny; 2 CTAs/SM (reg-bound)

// allocation-free scratch
__device__ float  g_denom[NROWS];
__device__ float  g_sppos[NROWS];
__device__ double g_total;
__device__ unsigned int g_count;
__device__ uint8_t g_f8[NROWS * DDIM];    // 2 MB e4m3, L2-resident

// ---------------- helpers ----------------
__device__ __forceinline__ uint32_t smem_u32(const void* p) {
    uint32_t a;
    asm("{ .reg .u64 t; cvta.to.shared.u64 t, %1; cvt.u32.u64 %0, t; }" : "=r"(a) : "l"(p));
    return a;
}
#define LDSM4(r, addr) \
    asm volatile("ldmatrix.sync.aligned.m8n8.x4.shared.b16 {%0,%1,%2,%3}, [%4];" \
        : "=r"((r)[0]), "=r"((r)[1]), "=r"((r)[2]), "=r"((r)[3]) : "r"(addr))
#define MMAFP8(d, a, b0, b1) \
    asm volatile("mma.sync.aligned.m16n8k32.row.col.f32.e4m3.e4m3.f32 " \
        "{%0,%1,%2,%3}, {%4,%5,%6,%7}, {%8,%9}, {%0,%1,%2,%3};" \
        : "+f"((d)[0]), "+f"((d)[1]), "+f"((d)[2]), "+f"((d)[3]) \
        : "r"((a)[0]), "r"((a)[1]), "r"((a)[2]), "r"((a)[3]), "r"(b0), "r"(b1))

// 128x128 e4m3 tile: smem row = 128B (8 x 16B chunks), chunk c stored at c ^ (row & 7)
__device__ __forceinline__ void load_tile_async(uint32_t sdst, const uint8_t* gsrc, int tid) {
    #pragma unroll
    for (int it = 0; it < 4; it++) {
        int i = tid + it * THREADS;          // 0..1023
        int row = i >> 3, c = i & 7;
        uint32_t dst = sdst + (uint32_t)(row * 128 + ((c ^ (row & 7)) * 16));
        const void* src = gsrc + (size_t)row * DDIM + c * 16;
        asm volatile("cp.async.cg.shared.global [%0], [%1], 16;" :: "r"(dst), "l"(src));
    }
}
#define CP_COMMIT() asm volatile("cp.async.commit_group;" ::: "memory")
#define CP_WAIT0()  asm volatile("cp.async.wait_group 0;" ::: "memory")

// ---------------- convert (fp32 -> e4m3) + init ----------------
__global__ void convert_kernel(const float* __restrict__ za, const float* __restrict__ zb) {
    int i4 = blockIdx.x * blockDim.x + threadIdx.x;
    if (i4 < NROWS) g_denom[i4] = 0.0f;
    if (i4 == 0) { g_total = 0.0; g_count = 0u; }
    if (i4 >= NROWS * DDIM / 4) return;
    float4 v = (i4 < BDIM * DDIM / 4) ? ((const float4*)za)[i4]
                                      : ((const float4*)zb)[i4 - BDIM * DDIM / 4];
    uint32_t packed;
    asm("{ .reg .b16 lo, hi;\n\t"
        "cvt.rn.satfinite.e4m3x2.f32 lo, %2, %1;\n\t"    // lo = {y, x} -> bytes [x][y]
        "cvt.rn.satfinite.e4m3x2.f32 hi, %4, %3;\n\t"    // hi = {w, z} -> bytes [z][w]
        "mov.b32 %0, {lo, hi}; }"
        : "=r"(packed) : "f"(v.x), "f"(v.y), "f"(v.z), "f"(v.w));
    ((uint32_t*)g_f8)[i4] = packed;
}

// ---------------- exact fp32 positive pairs (one warp per pair) ----------------
__global__ void pos_kernel(const float* __restrict__ za, const float* __restrict__ zb) {
    const int r    = blockIdx.x * 8 + (threadIdx.x >> 5);   // 0..8191
    const int lane = threadIdx.x & 31;
    float4 a = ((const float4*)(za + (size_t)r * DDIM))[lane];
    float4 b = ((const float4*)(zb + (size_t)r * DDIM))[lane];
    float s = a.x * b.x + a.y * b.y + a.z * b.z + a.w * b.w;
    #pragma unroll
    for (int o = 16; o > 0; o >>= 1) s += __shfl_xor_sync(0xffffffffu, s, o);
    if (lane == 0) {
        float x = s + s;                                    // sim / tau
        float sp = (x > 15.0f) ? x : log1pf(expf(x));       // accurate fp32 softplus
        g_sppos[r] = sp;
        g_sppos[r + BDIM] = sp;                             // symmetric pair
    }
}

// ---------------- fused triangular kernel (R6 structure, fp8) ----------------
template<bool DIAG>
__device__ __forceinline__ void tile_work(int bi, int bj, char* smem, uint32_t sbase, int tid) {
    const int lane   = tid & 31;
    const int wid    = tid >> 5;
    const int warp_m = wid & 3;            // 4 row blocks of 32
    const int warp_n = wid >> 2;           // 2 col blocks of 64

    load_tile_async(sbase + SM_A, g_f8 + (size_t)bi * 128 * DDIM, tid);
    load_tile_async(sbase + SM_B, g_f8 + (size_t)bj * 128 * DDIM, tid);
    CP_COMMIT();
    CP_WAIT0();
    __syncthreads();

    const int a_row = warp_m * 32 + (lane & 7) + ((lane >> 3) & 1) * 8;   // + mt*16
    const int a_kc  = lane >> 4;           // 16B chunk within 32B k-step
    const int b_row = warp_n * 64 + (lane & 7) + ((lane >> 4) & 1) * 8;   // + g*16
    const int b_kc  = (lane >> 3) & 1;

    float acc[2][8][4];
    #pragma unroll
    for (int mt = 0; mt < 2; mt++)
        #pragma unroll
        for (int nl = 0; nl < 8; nl++)
            #pragma unroll
            for (int i = 0; i < 4; i++) acc[mt][nl][i] = 0.f;

    #pragma unroll
    for (int ks = 0; ks < 4; ks++) {       // 4 k-steps of 32
        uint32_t a[2][4], b[4][4];
        #pragma unroll
        for (int mt = 0; mt < 2; mt++) {
            int row = a_row + mt * 16;
            int ch  = (ks * 2 + a_kc) ^ (row & 7);
            LDSM4(a[mt], sbase + SM_A + (uint32_t)(row * 128 + ch * 16));
        }
        #pragma unroll
        for (int g = 0; g < 4; g++) {
            int row = b_row + g * 16;
            int ch  = (ks * 2 + b_kc) ^ (row & 7);
            LDSM4(b[g], sbase + SM_B + (uint32_t)(row * 128 + ch * 16));
        }
        #pragma unroll
        for (int mt = 0; mt < 2; mt++)
            #pragma unroll
            for (int nl = 0; nl < 8; nl++)
                MMAFP8(acc[mt][nl], a[mt], b[nl >> 1][(nl & 1) * 2], b[nl >> 1][(nl & 1) * 2 + 1]);
    }

    // ---- fused epilogue ----
    float rsum[2][2] = {{0.f, 0.f}, {0.f, 0.f}};
    float csum[16];
    #pragma unroll
    for (int c = 0; c < 16; c++) csum[c] = 0.f;

    #pragma unroll
    for (int mt = 0; mt < 2; mt++)
        #pragma unroll
        for (int nl = 0; nl < 8; nl++)
            #pragma unroll
            for (int i = 0; i < 4; i++) {
                float v = acc[mt][nl][i];
                float x = v + v;                              // sim / tau, tau = 0.5
                float e;
                asm("ex2.approx.ftz.f32 %0, %1;" : "=f"(e) : "f"(v * 2.8853900817779268f));
                float l;
                asm("lg2.approx.ftz.f32 %0, %1;" : "=f"(l) : "f"(1.0f + e));
                float sp  = 0.6931471805599453f * l;
                float spn = __fmaf_rn(-0.5f * e, e, e);       // x << 0: e^x - e^2x/2
                sp = (x < -9.0f) ? spn : sp;
                sp = (x > 15.0f) ? x : sp;
                if (DIAG) {
                    const int lr = warp_m * 32 + mt * 16 + (lane >> 2) + (i >> 1) * 8;
                    const int lc = warp_n * 64 + nl * 8 + (lane & 3) * 2 + (i & 1);
                    if (lr == lc) sp = 0.0f;                  // zero diagonal
                }
                rsum[mt][i >> 1] += sp;
                csum[nl * 2 + (i & 1)] += sp;
            }

    // ---- reductions via dedicated smem ----
    float* srow = (float*)(smem + SM_RED);          // [2][128]
    float* scol = (float*)(smem + SM_RED + 1024);   // [4][128]
    #pragma unroll
    for (int mt = 0; mt < 2; mt++)
        #pragma unroll
        for (int h = 0; h < 2; h++) {
            float v = rsum[mt][h];
            v += __shfl_xor_sync(0xffffffffu, v, 1);
            v += __shfl_xor_sync(0xffffffffu, v, 2);
            if ((lane & 3) == 0)
                srow[warp_n * 128 + warp_m * 32 + mt * 16 + (lane >> 2) + h * 8] = v;
        }
    if (!DIAG) {
        #pragma unroll
        for (int c = 0; c < 16; c++) {
            float v = csum[c];
            v += __shfl_xor_sync(0xffffffffu, v, 4);
            v += __shfl_xor_sync(0xffffffffu, v, 8);
            v += __shfl_xor_sync(0xffffffffu, v, 16);
            if (lane < 4)
                scol[warp_m * 128 + warp_n * 64 + (c >> 1) * 8 + lane * 2 + (c & 1)] = v;
        }
    }
    __syncthreads();
    if (tid < 128) {
        float rt = srow[tid] + srow[128 + tid];
        atomicAdd(&g_denom[bi * 128 + tid], rt);
        if (!DIAG) {
            float ct = scol[tid] + scol[128 + tid] + scol[256 + tid] + scol[384 + tid];
            atomicAdd(&g_denom[bj * 128 + tid], ct);
        }
    }
}

__global__ __launch_bounds__(THREADS, 2)
void fused_tri_kernel() {
    // exact rectangle -> upper-triangle map: 129 x 64 = 8256 CTAs, zero waste
    const int p = blockIdx.y;              // 0..63
    const int q = blockIdx.x;              // 0..128
    int bi = p, bj = p + q;
    if (bj >= 128) { bi = 127 - p; bj = q - 1; }
    extern __shared__ char smem[];
    const uint32_t sbase = smem_u32(smem);
    if (bi == bj) tile_work<true >(bi, bj, smem, sbase, threadIdx.x);
    else          tile_work<false>(bi, bj, smem, sbase, threadIdx.x);
}

// ---------------- parallel finalize (last block writes out) ----------------
__global__ void finalize_part(float* __restrict__ out) {
    __shared__ double red[256];
    const int i = blockIdx.x * 256 + threadIdx.x;     // 64*256 == NROWS exactly
    float spp = fmaxf(g_sppos[i], 1e-8f);
    float den = fmaxf(g_denom[i], 1e-8f);
    red[threadIdx.x] = (double)(logf(spp) - logf(den));
    __syncthreads();
    for (int o = 128; o > 0; o >>= 1) {
        if (threadIdx.x < o) red[threadIdx.x] += red[threadIdx.x + o];
        __syncthreads();
    }
    if (threadIdx.x == 0) {
        atomicAdd(&g_total, red[0]);
        __threadfence();
        unsigned int done = atomicAdd(&g_count, 1u);
        if (done == 63u) {
            __threadfence();
            double tot = *((volatile double*)&g_total);
            out[0] = (float)(-tot / (double)NROWS);
        }
    }
}

extern "C" void kernel_launch(void* const* d_in, const int* in_sizes, int n_in,
                              void* d_out, int out_size) {
    const float* za = (const float*)d_in[0];
    const float* zb = (const float*)d_in[1];
    float* out = (float*)d_out;

    cudaFuncSetAttribute(fused_tri_kernel, cudaFuncAttributeMaxDynamicSharedMemorySize, SM_TOTAL);

    convert_kernel<<<(NROWS * DDIM / 4 + 255) / 256, 256>>>(za, zb);
    pos_kernel<<<BDIM / 8, 256>>>(za, zb);
    dim3 grid(129, 64);                   // exact triangular cover
    fused_tri_kernel<<<grid, THREADS, SM_TOTAL>>>();
    finalize_part<<<64, 256>>>(out);
}